// round 4
// baseline (speedup 1.0000x reference)
#include <cuda_runtime.h>

#define BB 256
#define CC 700
#define TT 500
#define NN 512
#define OO 20
#define CP 704
#define NCTAS 128
#define NTH 256

// dynamic smem: floats Ws[128][36], w4s[512][20]; uints smA/B/C[32][16], sw[32]
#define WS_F (128 * 36)
#define W4S_F (512 * OO)
#define SMEM_BYTES ((WS_F + W4S_F + 3 * 512 + 32) * 4)

__device__ float g_W1t[(size_t)CP * NN];
__device__ float g_Wr2t[(size_t)NN * NN];
__device__ float g_W2t[(size_t)NN * NN];
__device__ float g_W3t[(size_t)NN * NN];
__device__ float g_Wr3t[(size_t)NN * NN];
__device__ float g_W4t[(size_t)NN * OO];
__device__ float g_H1[(size_t)TT * BB * NN];
__device__ unsigned g_sp[3][2][BB * 16];
__device__ unsigned g_barcnt;
__device__ volatile unsigned g_barphase;

__device__ __forceinline__ void grid_barrier() {
    __threadfence();
    __syncthreads();
    if (threadIdx.x == 0) {
        unsigned gen = g_barphase;
        if (atomicAdd(&g_barcnt, 1u) == gridDim.x - 1) {
            g_barcnt = 0u;
            __threadfence();
            g_barphase = gen + 1u;
        } else {
            while (g_barphase == gen) __nanosleep(64);
        }
        __threadfence();
    }
    __syncthreads();
}

__global__ void prep_kernel(
    const float* __restrict__ W1, const float* __restrict__ W2,
    const float* __restrict__ Wr2, const float* __restrict__ W3,
    const float* __restrict__ Wr3, const float* __restrict__ W4)
{
    const int tid = blockIdx.x * blockDim.x + threadIdx.x;
    const int str = gridDim.x * blockDim.x;
    for (int i = tid; i < CP * NN; i += str) {
        int c = i >> 9, n = i & 511;
        g_W1t[i] = (c < CC) ? W1[(size_t)n * CC + c] : 0.f;
    }
    for (int i = tid; i < NN * NN; i += str) {
        int k = i >> 9, n = i & 511;
        size_t j = (size_t)n * NN + k;
        g_Wr2t[i] = Wr2[j]; g_W2t[i] = W2[j]; g_W3t[i] = W3[j]; g_Wr3t[i] = Wr3[j];
    }
    for (int i = tid; i < NN * OO; i += str)
        g_W4t[i] = W4[(size_t)(i % OO) * NN + (i / OO)];
    for (int i = tid; i < 3 * 2 * BB * 16; i += str) (&g_sp[0][0][0])[i] = 0u;
    if (tid == 0) { g_barcnt = 0u; g_barphase = 0u; }
}

// H1[t][b][n] = sum_c x[b][c][t] * W1[n][c]  (pure dot, ascending-c FFMA chain)
__global__ __launch_bounds__(256, 2) void h1_gemm_kernel(const float* __restrict__ x)
{
    __shared__ float As[8][64], Bs[8][64];
    const int b = blockIdx.z, t0 = blockIdx.y * 64, n0 = blockIdx.x * 64;
    const int tx = threadIdx.x & 15, ty = threadIdx.x >> 4;
    const float* __restrict__ xb = x + (size_t)b * CC * TT;
    float acc[4][4] = {};
    for (int c0 = 0; c0 < CP; c0 += 8) {
        for (int i = threadIdx.x; i < 512; i += 256) {
            int kc = i >> 6, t2 = i & 63, c = c0 + kc, t = t0 + t2;
            As[kc][t2] = (c < CC && t < TT) ? xb[(size_t)c * TT + t] : 0.f;
            Bs[kc][t2] = g_W1t[(size_t)c * NN + n0 + t2];
        }
        __syncthreads();
#pragma unroll
        for (int kc = 0; kc < 8; ++kc) {
            float av[4], bv[4];
#pragma unroll
            for (int j = 0; j < 4; ++j) { av[j] = As[kc][ty + 16 * j]; bv[j] = Bs[kc][tx + 16 * j]; }
#pragma unroll
            for (int i = 0; i < 4; ++i)
#pragma unroll
                for (int j = 0; j < 4; ++j) acc[i][j] = __fmaf_rn(av[i], bv[j], acc[i][j]);
        }
        __syncthreads();
    }
#pragma unroll
    for (int i = 0; i < 4; ++i) {
        int t = t0 + ty + 16 * i;
        if (t < TT)
#pragma unroll
            for (int j = 0; j < 4; ++j)
                g_H1[((size_t)t * BB + b) * NN + n0 + tx + 16 * j] = acc[i][j];
    }
}

// sparse gather = binary GEMM, strictly ascending k (bit-exact vs fp32 FFMA chain)
template <bool DUAL>
__device__ __forceinline__ void gather_gemm(
    const float* __restrict__ Wt,
    const unsigned* __restrict__ smX, const unsigned* __restrict__ smY,
    float (*__restrict__ Ws)[36],
    int bl, int nl, int n0, int tid, float* aX, float* aY)
{
#pragma unroll 1
    for (int kc = 0; kc < 4; ++kc) {
        const float* __restrict__ src = Wt + (size_t)(kc * 128) * NN + n0;
#pragma unroll
        for (int i = 0; i < 16; ++i) {
            int idx = tid + i * NTH, r = idx >> 5, c = idx & 31;
            Ws[r][c] = src[(size_t)r * NN + c];
        }
        __syncthreads();
#pragma unroll
        for (int w = 0; w < 4; ++w) {
            unsigned m = smX[bl * 16 + kc * 4 + w];
            while (m) {
                int j = __ffs(m) - 1; m &= m - 1u;
                const float4 wv = *(const float4*)&Ws[w * 32 + j][nl];
                aX[0] = __fadd_rn(aX[0], wv.x); aX[1] = __fadd_rn(aX[1], wv.y);
                aX[2] = __fadd_rn(aX[2], wv.z); aX[3] = __fadd_rn(aX[3], wv.w);
            }
            if (DUAL) {
                unsigned my = smY[bl * 16 + kc * 4 + w];
                while (my) {
                    int j = __ffs(my) - 1; my &= my - 1u;
                    const float4 wv = *(const float4*)&Ws[w * 32 + j][nl];
                    aY[0] = __fadd_rn(aY[0], wv.x); aY[1] = __fadd_rn(aY[1], wv.y);
                    aY[2] = __fadd_rn(aY[2], wv.z); aY[3] = __fadd_rn(aY[3], wv.w);
                }
            }
        }
        __syncthreads();
    }
}

// LIF: m = ((tau*m)*(1-s))+h, separate roundings (matches XLA mul/mul/add)
__device__ __forceinline__ unsigned lif4(float* m, const float* tau, const float* vth,
                                         const float* h, float* s, float* cnt)
{
    unsigned nib = 0u;
#pragma unroll
    for (int j = 0; j < 4; ++j) {
        float one_ms = __fadd_rn(1.f, -s[j]);                       // exact (s in {0,1})
        m[j] = __fadd_rn(__fmul_rn(__fmul_rn(tau[j], m[j]), one_ms), h[j]);
        float sp = (__fadd_rn(m[j], -vth[j]) > 0.f) ? 1.f : 0.f;
        cnt[j] += sp; s[j] = sp;
        nib |= ((unsigned)sp) << j;
    }
    return nib;
}

__global__ __launch_bounds__(NTH, 1) void rsnn_recurrent_kernel(
    float* __restrict__ out,
    const float* __restrict__ b1, const float* __restrict__ br2,
    const float* __restrict__ b2, const float* __restrict__ b3,
    const float* __restrict__ br3, const float* __restrict__ b4,
    const float* __restrict__ Vth1, const float* __restrict__ tau1,
    const float* __restrict__ Vth2, const float* __restrict__ tau2,
    const float* __restrict__ Vth3, const float* __restrict__ tau3)
{
    extern __shared__ float dyn[];
    float (*Ws)[36] = (float(*)[36])dyn;
    float* w4s = dyn + WS_F;                       // [512][OO]
    unsigned* smA = (unsigned*)(dyn + WS_F + W4S_F);
    unsigned* smB = smA + 512;                     // [32][16]
    unsigned* smC = smB + 512;
    unsigned* sw  = smC + 512;

    const int tid = threadIdx.x;
    const int bt = blockIdx.x >> 4, ns = blockIdx.x & 15;
    const int b0 = bt * 32, n0 = ns * 32;
    const int bl = tid >> 3, nq = tid & 7, nl = nq * 4;
    const int b = b0 + bl, n = n0 + nl;

    for (int i = tid; i < 512 * OO; i += NTH) w4s[i] = g_W4t[i];

    float ta1[4], ta2[4], ta3[4], vt1[4], vt2[4], vt3[4];
    float bb1[4], bb2[4], bb3[4], br2v[4], br3v[4];
    *(float4*)ta1 = *(const float4*)(tau1 + n); *(float4*)vt1 = *(const float4*)(Vth1 + n);
    *(float4*)ta2 = *(const float4*)(tau2 + n); *(float4*)vt2 = *(const float4*)(Vth2 + n);
    *(float4*)ta3 = *(const float4*)(tau3 + n); *(float4*)vt3 = *(const float4*)(Vth3 + n);
    *(float4*)bb1 = *(const float4*)(b1 + n);   *(float4*)bb2 = *(const float4*)(b2 + n);
    *(float4*)bb3 = *(const float4*)(b3 + n);
    *(float4*)br2v = *(const float4*)(br2 + n); *(float4*)br3v = *(const float4*)(br3 + n);

    float m1[4] = {}, m2[4] = {}, m3[4] = {};
    float s1[4] = {}, s2[4] = {}, s3[4] = {};
    float c1[4] = {}, c2[4] = {}, c3[4] = {};
    float r2[4], r3[4];

    for (int t = 0; t <= TT; ++t) {
        const int parw = t & 1, parr = parw ^ 1;

        for (int i = tid; i < 512; i += NTH) {
            int gi = (b0 + (i >> 4)) * 16 + (i & 15);
            smA[i] = g_sp[0][parr][gi];
            smB[i] = g_sp[1][parr][gi];
            smC[i] = g_sp[2][parr][gi];
        }
        __syncthreads();

        // output for step t-1: one full ascending-k chain per (b,o), then +b4
        if (t > 0 && tid < 40) {
            int p = ns * 40 + tid;
            int bb = p / OO, o = p % OO;
            float acc = 0.f;
#pragma unroll 1
            for (int w = 0; w < 16; ++w) {
                unsigned word = smC[bb * 16 + w];
#pragma unroll
                for (int j = 0; j < 32; ++j) {
                    float sel = (word & (1u << j)) ? w4s[(w * 32 + j) * OO + o] : 0.f;
                    acc = __fadd_rn(acc, sel);
                }
            }
            out[((size_t)(b0 + bb) * OO + o) * TT + (t - 1)] = __fadd_rn(acc, b4[o]);
        }
        if (t == TT) break;
        __syncthreads();

        // Phase 1: r1 = Wr2.s1_prev, r2 = Wr2.s2_prev, r3 = Wr3.s3_prev
        float r1[4] = {};
        r2[0] = r2[1] = r2[2] = r2[3] = 0.f;
        r3[0] = r3[1] = r3[2] = r3[3] = 0.f;
        gather_gemm<true >(g_Wr2t, smA, smB, Ws, bl, nl, n0, tid, r1, r2);
        gather_gemm<false>(g_Wr3t, smC, smC, Ws, bl, nl, n0, tid, r3, r3);

        float h[4];
        const float4 h1v = *(const float4*)&g_H1[((size_t)t * BB + b) * NN + n];
        const float d1[4] = {h1v.x, h1v.y, h1v.z, h1v.w};
#pragma unroll
        for (int j = 0; j < 4; ++j)   // ((d1 + b1) + r1) + br2
            h[j] = __fadd_rn(__fadd_rn(__fadd_rn(d1[j], bb1[j]), r1[j]), br2v[j]);
        unsigned nib = lif4(m1, ta1, vt1, h, s1, c1);

        if (tid < 32) sw[tid] = 0u;
        __syncthreads();
        atomicOr(&sw[bl], nib << (nq * 4));
        __syncthreads();
        if (tid < 32) g_sp[0][parw][(b0 + tid) * 16 + ns] = sw[tid];
        grid_barrier();

        // Phase 2: a2 = W2.s1(t)
        for (int i = tid; i < 512; i += NTH)
            smA[i] = g_sp[0][parw][(b0 + (i >> 4)) * 16 + (i & 15)];
        __syncthreads();
        float a2[4] = {};
        gather_gemm<false>(g_W2t, smA, smA, Ws, bl, nl, n0, tid, a2, a2);
#pragma unroll
        for (int j = 0; j < 4; ++j)   // ((a2 + b2) + r2) + br2
            h[j] = __fadd_rn(__fadd_rn(__fadd_rn(a2[j], bb2[j]), r2[j]), br2v[j]);
        nib = lif4(m2, ta2, vt2, h, s2, c2);

        if (tid < 32) sw[tid] = 0u;
        __syncthreads();
        atomicOr(&sw[bl], nib << (nq * 4));
        __syncthreads();
        if (tid < 32) g_sp[1][parw][(b0 + tid) * 16 + ns] = sw[tid];
        grid_barrier();

        // Phase 3: a3 = W3.s2(t)
        for (int i = tid; i < 512; i += NTH)
            smB[i] = g_sp[1][parw][(b0 + (i >> 4)) * 16 + (i & 15)];
        __syncthreads();
        float a3[4] = {};
        gather_gemm<false>(g_W3t, smB, smB, Ws, bl, nl, n0, tid, a3, a3);
#pragma unroll
        for (int j = 0; j < 4; ++j)   // ((a3 + b3) + r3) + br3
            h[j] = __fadd_rn(__fadd_rn(__fadd_rn(a3[j], bb3[j]), r3[j]), br3v[j]);
        nib = lif4(m3, ta3, vt3, h, s3, c3);

        if (tid < 32) sw[tid] = 0u;
        __syncthreads();
        atomicOr(&sw[bl], nib << (nq * 4));
        __syncthreads();
        if (tid < 32) g_sp[2][parw][(b0 + tid) * 16 + ns] = sw[tid];
        grid_barrier();
    }

    const double invd = 1.0 / (double)TT;
    const float iT = (float)invd;
    const size_t base = (size_t)BB * OO * TT, off = (size_t)b * NN + n;
#pragma unroll
    for (int j = 0; j < 4; ++j) {
        out[base + off + j]                       = __fmul_rn(c1[j], iT);
        out[base + (size_t)BB * NN + off + j]     = __fmul_rn(c2[j], iT);
        out[base + 2 * (size_t)BB * NN + off + j] = __fmul_rn(c3[j], iT);
    }
}

extern "C" void kernel_launch(void* const* d_in, const int* in_sizes, int n_in,
                              void* d_out, int out_size)
{
    const float* x   = (const float*)d_in[0];
    const float* W1  = (const float*)d_in[1];
    const float* b1  = (const float*)d_in[2];
    const float* W2  = (const float*)d_in[3];
    const float* b2  = (const float*)d_in[4];
    const float* Wr2 = (const float*)d_in[5];
    const float* br2 = (const float*)d_in[6];
    const float* W3  = (const float*)d_in[7];
    const float* b3  = (const float*)d_in[8];
    const float* Wr3 = (const float*)d_in[9];
    const float* br3 = (const float*)d_in[10];
    const float* W4  = (const float*)d_in[11];
    const float* b4  = (const float*)d_in[12];
    const float* Vth1 = (const float*)d_in[13];
    const float* tau1 = (const float*)d_in[14];
    const float* Vth2 = (const float*)d_in[15];
    const float* tau2 = (const float*)d_in[16];
    const float* Vth3 = (const float*)d_in[17];
    const float* tau3 = (const float*)d_in[18];
    float* out = (float*)d_out;

    static int smem_set = 0;
    if (!smem_set) {
        cudaFuncSetAttribute(rsnn_recurrent_kernel,
                             cudaFuncAttributeMaxDynamicSharedMemorySize, SMEM_BYTES);
        smem_set = 1;
    }

    prep_kernel<<<256, 256>>>(W1, W2, Wr2, W3, Wr3, W4);
    dim3 g(NN / 64, (TT + 63) / 64, BB);
    h1_gemm_kernel<<<g, 256>>>(x);
    rsnn_recurrent_kernel<<<NCTAS, NTH, SMEM_BYTES>>>(
        out, b1, br2, b2, b3, br3, b4, Vth1, tau1, Vth2, tau2, Vth3, tau3);
}

// round 5
// speedup vs baseline: 1.1679x; 1.1679x over previous
#include <cuda_runtime.h>

#define BB 256
#define CC 700
#define TT 500
#define NN 512
#define OO 20
#define CP 704
#define NCTAS 128
#define NTH 256
#define NGRP 8          // batch groups (bt)
#define GSZ 16          // CTAs per group (ns)

// dynamic smem layout (floats): sWr2[512][36], sW2[512][36], Ws[128][36],
// w4s[512][20], then uints smA/B/C[512], sw[32]
#define RES_F (512 * 36)
#define WS_F (128 * 36)
#define W4S_F (512 * OO)
#define SMEM_BYTES ((2 * RES_F + WS_F + W4S_F + 3 * 512 + 32) * 4)

__device__ float g_W1t[(size_t)CP * NN];
__device__ float g_Wr2t[(size_t)NN * NN];
__device__ float g_W2t[(size_t)NN * NN];
__device__ float g_W3t[(size_t)NN * NN];
__device__ float g_Wr3t[(size_t)NN * NN];
__device__ float g_W4t[(size_t)NN * OO];
__device__ float g_H1[(size_t)TT * BB * NN];
__device__ unsigned g_sp[3][2][BB * 16];
__device__ unsigned g_gcnt[NGRP * 32];            // 128B-padded per-group counters
__device__ volatile unsigned g_gphz[NGRP * 32];

__device__ __forceinline__ void group_barrier(int bt) {
    __threadfence();
    __syncthreads();
    if (threadIdx.x == 0) {
        const int gi = bt * 32;
        unsigned gen = g_gphz[gi];
        if (atomicAdd(&g_gcnt[gi], 1u) == GSZ - 1) {
            g_gcnt[gi] = 0u;
            __threadfence();
            g_gphz[gi] = gen + 1u;
        } else {
            while (g_gphz[gi] == gen) __nanosleep(32);
        }
        __threadfence();
    }
    __syncthreads();
}

__global__ void prep_kernel(
    const float* __restrict__ W1, const float* __restrict__ W2,
    const float* __restrict__ Wr2, const float* __restrict__ W3,
    const float* __restrict__ Wr3, const float* __restrict__ W4)
{
    const int tid = blockIdx.x * blockDim.x + threadIdx.x;
    const int str = gridDim.x * blockDim.x;
    for (int i = tid; i < CP * NN; i += str) {
        int c = i >> 9, n = i & 511;
        g_W1t[i] = (c < CC) ? W1[(size_t)n * CC + c] : 0.f;
    }
    for (int i = tid; i < NN * NN; i += str) {
        int k = i >> 9, n = i & 511;
        size_t j = (size_t)n * NN + k;
        g_Wr2t[i] = Wr2[j]; g_W2t[i] = W2[j]; g_W3t[i] = W3[j]; g_Wr3t[i] = Wr3[j];
    }
    for (int i = tid; i < NN * OO; i += str)
        g_W4t[i] = W4[(size_t)(i % OO) * NN + (i / OO)];
    for (int i = tid; i < 3 * 2 * BB * 16; i += str) (&g_sp[0][0][0])[i] = 0u;
    for (int i = tid; i < NGRP * 32; i += str) { g_gcnt[i] = 0u; g_gphz[i] = 0u; }
}

// H1[t][b][n] = sum_c x[b][c][t] * W1[n][c]  (ascending-c FFMA chain)
// 128(t) x 128(n) tile, 256 threads, 8x8 per thread, register-prefetch pipeline
__global__ __launch_bounds__(256, 2) void h1_gemm_kernel(const float* __restrict__ x)
{
    __shared__ float As[8][128], Bs[8][128];
    const int n0 = blockIdx.x * 128, t0 = blockIdx.y * 128, b = blockIdx.z;
    const int tx = threadIdx.x & 15, ty = threadIdx.x >> 4;
    const float* __restrict__ xb = x + (size_t)b * CC * TT;
    float acc[8][8] = {};
    float ra[4], rb[4];

#define H1_LOAD(c0)                                                          \
    _Pragma("unroll")                                                        \
    for (int u = 0; u < 4; ++u) {                                            \
        int i = threadIdx.x + u * 256, kc = i >> 7, e = i & 127;             \
        int c = (c0) + kc, t = t0 + e;                                       \
        ra[u] = (c < CC && t < TT) ? xb[(size_t)c * TT + t] : 0.f;           \
        rb[u] = g_W1t[(size_t)c * NN + n0 + e];                              \
    }

    H1_LOAD(0)
    for (int c0 = 0; c0 < CP; c0 += 8) {
#pragma unroll
        for (int u = 0; u < 4; ++u) {
            int i = threadIdx.x + u * 256;
            As[i >> 7][i & 127] = ra[u];
            Bs[i >> 7][i & 127] = rb[u];
        }
        __syncthreads();
        if (c0 + 8 < CP) { H1_LOAD(c0 + 8) }
#pragma unroll
        for (int kc = 0; kc < 8; ++kc) {
            float av[8], bv[8];
            *(float4*)av       = *(const float4*)&As[kc][ty * 8];
            *(float4*)(av + 4) = *(const float4*)&As[kc][ty * 8 + 4];
            *(float4*)bv       = *(const float4*)&Bs[kc][tx * 8];
            *(float4*)(bv + 4) = *(const float4*)&Bs[kc][tx * 8 + 4];
#pragma unroll
            for (int i = 0; i < 8; ++i)
#pragma unroll
                for (int j = 0; j < 8; ++j)
                    acc[i][j] = __fmaf_rn(av[i], bv[j], acc[i][j]);
        }
        __syncthreads();
    }
#pragma unroll
    for (int i = 0; i < 8; ++i) {
        int t = t0 + ty * 8 + i;
        if (t < TT) {
            float* dst = &g_H1[((size_t)t * BB + b) * NN + n0 + tx * 8];
            *(float4*)dst       = *(float4*)&acc[i][0];
            *(float4*)(dst + 4) = *(float4*)&acc[i][4];
        }
    }
}

// staged gather (weights streamed through Ws in 128-k chunks), ascending k
__device__ __forceinline__ void gather_staged(
    const float* __restrict__ Wt, const unsigned* __restrict__ smX,
    float (*__restrict__ Ws)[36], int bl, int nl, int n0, int tid, float* aX)
{
#pragma unroll 1
    for (int kc = 0; kc < 4; ++kc) {
        const float* __restrict__ src = Wt + (size_t)(kc * 128) * NN + n0;
#pragma unroll
        for (int i = 0; i < 16; ++i) {
            int idx = tid + i * NTH;
            Ws[idx >> 5][idx & 31] = src[(size_t)(idx >> 5) * NN + (idx & 31)];
        }
        __syncthreads();
#pragma unroll
        for (int w = 0; w < 4; ++w) {
            unsigned m = smX[bl * 16 + kc * 4 + w];
            while (m) {
                int j = __ffs(m) - 1; m &= m - 1u;
                const float4 wv = *(const float4*)&Ws[w * 32 + j][nl];
                aX[0] = __fadd_rn(aX[0], wv.x); aX[1] = __fadd_rn(aX[1], wv.y);
                aX[2] = __fadd_rn(aX[2], wv.z); aX[3] = __fadd_rn(aX[3], wv.w);
            }
        }
        __syncthreads();
    }
}

// resident gather: weights already in smem, no syncs; optional dual mask
template <bool DUAL>
__device__ __forceinline__ void gather_res(
    const float* __restrict__ sW, const unsigned* __restrict__ smX,
    const unsigned* __restrict__ smY, int bl, int nl, float* aX, float* aY)
{
#pragma unroll 1
    for (int w = 0; w < 16; ++w) {
        const float* base = sW + (size_t)(w * 32) * 36 + nl;
        unsigned m = smX[bl * 16 + w];
        while (m) {
            int j = __ffs(m) - 1; m &= m - 1u;
            const float4 wv = *(const float4*)(base + j * 36);
            aX[0] = __fadd_rn(aX[0], wv.x); aX[1] = __fadd_rn(aX[1], wv.y);
            aX[2] = __fadd_rn(aX[2], wv.z); aX[3] = __fadd_rn(aX[3], wv.w);
        }
        if (DUAL) {
            unsigned my = smY[bl * 16 + w];
            while (my) {
                int j = __ffs(my) - 1; my &= my - 1u;
                const float4 wv = *(const float4*)(base + j * 36);
                aY[0] = __fadd_rn(aY[0], wv.x); aY[1] = __fadd_rn(aY[1], wv.y);
                aY[2] = __fadd_rn(aY[2], wv.z); aY[3] = __fadd_rn(aY[3], wv.w);
            }
        }
    }
}

// LIF: m = ((tau*m)*(1-s))+h, separate roundings
__device__ __forceinline__ unsigned lif4(float* m, const float* tau, const float* vth,
                                         const float* h, float* s, float* cnt)
{
    unsigned nib = 0u;
#pragma unroll
    for (int j = 0; j < 4; ++j) {
        float one_ms = __fadd_rn(1.f, -s[j]);
        m[j] = __fadd_rn(__fmul_rn(__fmul_rn(tau[j], m[j]), one_ms), h[j]);
        float sp = (__fadd_rn(m[j], -vth[j]) > 0.f) ? 1.f : 0.f;
        cnt[j] += sp; s[j] = sp;
        nib |= ((unsigned)sp) << j;
    }
    return nib;
}

__global__ __launch_bounds__(NTH, 1) void rsnn_recurrent_kernel(
    float* __restrict__ out,
    const float* __restrict__ b1, const float* __restrict__ br2,
    const float* __restrict__ b2, const float* __restrict__ b3,
    const float* __restrict__ br3, const float* __restrict__ b4,
    const float* __restrict__ Vth1, const float* __restrict__ tau1,
    const float* __restrict__ Vth2, const float* __restrict__ tau2,
    const float* __restrict__ Vth3, const float* __restrict__ tau3)
{
    extern __shared__ float dyn[];
    float* sWr2 = dyn;                       // [512][36]
    float* sW2  = dyn + RES_F;               // [512][36]
    float (*Ws)[36] = (float(*)[36])(dyn + 2 * RES_F);
    float* w4s = dyn + 2 * RES_F + WS_F;     // [512][OO]
    unsigned* smA = (unsigned*)(w4s + W4S_F);
    unsigned* smB = smA + 512;
    unsigned* smC = smB + 512;
    unsigned* sw  = smC + 512;

    const int tid = threadIdx.x;
    const int bt = blockIdx.x >> 4, ns = blockIdx.x & 15;
    const int b0 = bt * 32, n0 = ns * 32;
    const int bl = tid >> 3, nq = tid & 7, nl = nq * 4;
    const int b = b0 + bl, n = n0 + nl;

    // resident weight slices + W4
    for (int i = tid; i < 512 * 32; i += NTH) {
        int r = i >> 5, c = i & 31;
        sWr2[r * 36 + c] = g_Wr2t[(size_t)r * NN + n0 + c];
        sW2 [r * 36 + c] = g_W2t [(size_t)r * NN + n0 + c];
    }
    for (int i = tid; i < 512 * OO; i += NTH) w4s[i] = g_W4t[i];

    float ta1[4], ta2[4], ta3[4], vt1[4], vt2[4], vt3[4];
    float bb1[4], bb2[4], bb3[4], br2v[4], br3v[4];
    *(float4*)ta1 = *(const float4*)(tau1 + n); *(float4*)vt1 = *(const float4*)(Vth1 + n);
    *(float4*)ta2 = *(const float4*)(tau2 + n); *(float4*)vt2 = *(const float4*)(Vth2 + n);
    *(float4*)ta3 = *(const float4*)(tau3 + n); *(float4*)vt3 = *(const float4*)(Vth3 + n);
    *(float4*)bb1 = *(const float4*)(b1 + n);   *(float4*)bb2 = *(const float4*)(b2 + n);
    *(float4*)bb3 = *(const float4*)(b3 + n);
    *(float4*)br2v = *(const float4*)(br2 + n); *(float4*)br3v = *(const float4*)(br3 + n);

    float m1[4] = {}, m2[4] = {}, m3[4] = {};
    float s1[4] = {}, s2[4] = {}, s3[4] = {};
    float c1[4] = {}, c2[4] = {}, c3[4] = {};
    float r2[4], r3[4];
    __syncthreads();

    for (int t = 0; t <= TT; ++t) {
        const int parw = t & 1, parr = parw ^ 1;

        for (int i = tid; i < 512; i += NTH) {
            int gi = (b0 + (i >> 4)) * 16 + (i & 15);
            smA[i] = g_sp[0][parr][gi];
            smB[i] = g_sp[1][parr][gi];
            smC[i] = g_sp[2][parr][gi];
        }
        __syncthreads();

        // output for step t-1: full ascending-k chain per (b,o), then +b4
        if (t > 0 && tid < 40) {
            int p = ns * 40 + tid;
            int bb = p / OO, o = p % OO;
            float acc = 0.f;
#pragma unroll 1
            for (int w = 0; w < 16; ++w) {
                unsigned word = smC[bb * 16 + w];
#pragma unroll
                for (int j = 0; j < 32; ++j) {
                    float sel = (word & (1u << j)) ? w4s[(w * 32 + j) * OO + o] : 0.f;
                    acc = __fadd_rn(acc, sel);
                }
            }
            out[((size_t)(b0 + bb) * OO + o) * TT + (t - 1)] = __fadd_rn(acc, b4[o]);
        }
        if (t == TT) break;
        __syncthreads();

        // Phase 1: r1 = Wr2.s1p, r2 = Wr2.s2p (resident dual), r3 = Wr3.s3p (staged)
        float r1[4] = {};
        r2[0] = r2[1] = r2[2] = r2[3] = 0.f;
        r3[0] = r3[1] = r3[2] = r3[3] = 0.f;
        gather_res<true>(sWr2, smA, smB, bl, nl, r1, r2);
        gather_staged(g_Wr3t, smC, Ws, bl, nl, n0, tid, r3);

        float h[4];
        const float4 h1v = *(const float4*)&g_H1[((size_t)t * BB + b) * NN + n];
        const float d1[4] = {h1v.x, h1v.y, h1v.z, h1v.w};
#pragma unroll
        for (int j = 0; j < 4; ++j)   // ((d1 + b1) + r1) + br2
            h[j] = __fadd_rn(__fadd_rn(__fadd_rn(d1[j], bb1[j]), r1[j]), br2v[j]);
        unsigned nib = lif4(m1, ta1, vt1, h, s1, c1);

        if (tid < 32) sw[tid] = 0u;
        __syncthreads();
        atomicOr(&sw[bl], nib << (nq * 4));
        __syncthreads();
        if (tid < 32) g_sp[0][parw][(b0 + tid) * 16 + ns] = sw[tid];
        group_barrier(bt);

        // Phase 2: a2 = W2.s1(t) (resident)
        for (int i = tid; i < 512; i += NTH)
            smA[i] = g_sp[0][parw][(b0 + (i >> 4)) * 16 + (i & 15)];
        __syncthreads();
        float a2[4] = {};
        gather_res<false>(sW2, smA, smA, bl, nl, a2, a2);
#pragma unroll
        for (int j = 0; j < 4; ++j)
            h[j] = __fadd_rn(__fadd_rn(__fadd_rn(a2[j], bb2[j]), r2[j]), br2v[j]);
        nib = lif4(m2, ta2, vt2, h, s2, c2);

        if (tid < 32) sw[tid] = 0u;
        __syncthreads();
        atomicOr(&sw[bl], nib << (nq * 4));
        __syncthreads();
        if (tid < 32) g_sp[1][parw][(b0 + tid) * 16 + ns] = sw[tid];
        group_barrier(bt);

        // Phase 3: a3 = W3.s2(t) (staged)
        for (int i = tid; i < 512; i += NTH)
            smB[i] = g_sp[1][parw][(b0 + (i >> 4)) * 16 + (i & 15)];
        __syncthreads();
        float a3[4] = {};
        gather_staged(g_W3t, smB, Ws, bl, nl, n0, tid, a3);
#pragma unroll
        for (int j = 0; j < 4; ++j)
            h[j] = __fadd_rn(__fadd_rn(__fadd_rn(a3[j], bb3[j]), r3[j]), br3v[j]);
        nib = lif4(m3, ta3, vt3, h, s3, c3);

        if (tid < 32) sw[tid] = 0u;
        __syncthreads();
        atomicOr(&sw[bl], nib << (nq * 4));
        __syncthreads();
        if (tid < 32) g_sp[2][parw][(b0 + tid) * 16 + ns] = sw[tid];
        group_barrier(bt);
    }

    const float iT = 1.f / (float)TT;
    const size_t base = (size_t)BB * OO * TT, off = (size_t)b * NN + n;
#pragma unroll
    for (int j = 0; j < 4; ++j) {
        out[base + off + j]                       = __fmul_rn(c1[j], iT);
        out[base + (size_t)BB * NN + off + j]     = __fmul_rn(c2[j], iT);
        out[base + 2 * (size_t)BB * NN + off + j] = __fmul_rn(c3[j], iT);
    }
}

extern "C" void kernel_launch(void* const* d_in, const int* in_sizes, int n_in,
                              void* d_out, int out_size)
{
    const float* x   = (const float*)d_in[0];
    const float* W1  = (const float*)d_in[1];
    const float* b1  = (const float*)d_in[2];
    const float* W2  = (const float*)d_in[3];
    const float* b2  = (const float*)d_in[4];
    const float* Wr2 = (const float*)d_in[5];
    const float* br2 = (const float*)d_in[6];
    const float* W3  = (const float*)d_in[7];
    const float* b3  = (const float*)d_in[8];
    const float* Wr3 = (const float*)d_in[9];
    const float* br3 = (const float*)d_in[10];
    const float* W4  = (const float*)d_in[11];
    const float* b4  = (const float*)d_in[12];
    const float* Vth1 = (const float*)d_in[13];
    const float* tau1 = (const float*)d_in[14];
    const float* Vth2 = (const float*)d_in[15];
    const float* tau2 = (const float*)d_in[16];
    const float* Vth3 = (const float*)d_in[17];
    const float* tau3 = (const float*)d_in[18];
    float* out = (float*)d_out;

    cudaFuncSetAttribute(rsnn_recurrent_kernel,
                         cudaFuncAttributeMaxDynamicSharedMemorySize, SMEM_BYTES);

    prep_kernel<<<256, 256>>>(W1, W2, Wr2, W3, Wr3, W4);
    dim3 g(NN / 128, 4, BB);
    h1_gemm_kernel<<<g, 256>>>(x);
    rsnn_recurrent_kernel<<<NCTAS, NTH, SMEM_BYTES>>>(
        out, b1, br2, b2, b3, br3, b4, Vth1, tau1, Vth2, tau2, Vth3, tau3);
}